// round 15
// baseline (speedup 1.0000x reference)
#include <cuda_runtime.h>
#include <cstdint>

#define B_   2
#define S_   2048
#define DM_  1024
#define H_   16
#define D_   64
#define NB_  5
#define SCALE_ 0.125f
#define LOG2E_ 1.4426950408889634f
#define ALPHA_ (SCALE_ * LOG2E_)

// Static device scratch
__device__ float g_q[B_*H_*S_*D_];
__device__ float g_k[B_*H_*S_*D_];
__device__ float g_v[B_*H_*S_*D_];
__device__ float g_att[B_*S_*DM_];
__device__ float g_xr[4096*1024];
__device__ float g_wr[4][1024*1024];   // tf32-rounded W (k-major)
__device__ float g_part[2][4096*1024]; // split-K partials for out-proj

// ---------------------------------------------------------------------------
__device__ __forceinline__ unsigned f2tf(float x) {
    unsigned r;
    asm("cvt.rna.tf32.f32 %0, %1;" : "=r"(r) : "f"(x));
    return r;
}
__device__ __forceinline__ float f2tff(float x) { return __uint_as_float(f2tf(x)); }

__device__ __forceinline__ void mma8f(float* c, const float* a, float b0f, float b1f) {
    asm volatile(
        "mma.sync.aligned.m16n8k8.row.col.f32.tf32.tf32.f32 "
        "{%0,%1,%2,%3}, {%4,%5,%6,%7}, {%8,%9}, {%0,%1,%2,%3};"
        : "+f"(c[0]), "+f"(c[1]), "+f"(c[2]), "+f"(c[3])
        : "r"(__float_as_uint(a[0])), "r"(__float_as_uint(a[1])),
          "r"(__float_as_uint(a[2])), "r"(__float_as_uint(a[3])),
          "r"(__float_as_uint(b0f)), "r"(__float_as_uint(b1f)));
}

#define CP16(dst_smem, src) \
    asm volatile("cp.async.cg.shared.global [%0], [%1], 16;\n" :: \
        "r"((unsigned)__cvta_generic_to_shared(dst_smem)), "l"(src) : "memory")
#define CP_COMMIT() asm volatile("cp.async.commit_group;\n" ::: "memory")
#define CP_WAIT0()  asm volatile("cp.async.wait_group 0;\n" ::: "memory")
#define CP_WAIT1()  asm volatile("cp.async.wait_group 1;\n" ::: "memory")

// exp2 on FMA pipe, max-free softmax domain; clamps low at -60.
__device__ __forceinline__ float exp2p(float y) {
    y = fmaxf(y, -60.f);
    float t = y + 12582912.0f;           // 1.5*2^23 round-to-nearest
    float fl = t - 12582912.0f;
    float f = y - fl;                    // [-0.5, 0.5]
    float p = fmaf(1.5403530e-4f, f, 1.3333558e-3f);
    p = fmaf(p, f, 9.6181291e-3f);
    p = fmaf(p, f, 5.5504109e-2f);
    p = fmaf(p, f, 2.4022651e-1f);
    p = fmaf(p, f, 6.9314718e-1f);
    p = fmaf(p, f, 1.0f);
    int e = ((__float_as_int(t) & 0x7FFFFF) - 0x400000 + 127) << 23;
    return p * __int_as_float(e);
}

// ---------------------------------------------------------------------------
// Pre-pass: tf32-round x and the 4 weight matrices.
// ---------------------------------------------------------------------------
__global__ void round_pass(const float* __restrict__ x,  const float* __restrict__ wq,
                           const float* __restrict__ wk, const float* __restrict__ wv,
                           const float* __restrict__ wo)
{
    const int total = 1048576 + 4 * 262144;
    for (int i = blockIdx.x * blockDim.x + threadIdx.x; i < total;
         i += gridDim.x * blockDim.x) {
        const float4* src; float4* dst; int off;
        if (i < 1048576) { src = (const float4*)x; dst = (float4*)g_xr; off = i; }
        else {
            int j = i - 1048576; int seg = j >> 18; off = j & 262143;
            const float* s4 = (seg == 0) ? wq : (seg == 1) ? wk : (seg == 2) ? wv : wo;
            src = (const float4*)s4; dst = (float4*)g_wr[seg];
        }
        float4 v = src[off];
        v.x = f2tff(v.x); v.y = f2tff(v.y); v.z = f2tff(v.z); v.w = f2tff(v.w);
        dst[off] = v;
    }
}

// ---------------------------------------------------------------------------
// TF32 GEMM: block 128x128, 128 threads (4 warps, warp tile 64x64),
// k-step 32, 3-stage cp.async. mode: 0=plain+bias, 1=permute+round+bias,
// 2=partial (no bias, plain store).
// ---------------------------------------------------------------------------
struct GSmem {
    float Xs[3][128][36];
    float Ws[3][32][132];
};

__device__ __forceinline__ void gemm_body(
    GSmem& sm, const float* __restrict__ X, const float* __restrict__ W,
    const float* __restrict__ bias, float* __restrict__ out, int mode,
    int m0, int n0, int kbeg, int kiters)
{
    const int tid  = threadIdx.x;
    const int lane = tid & 31, wid = tid >> 5;
    const int qd = lane >> 2, lr = lane & 3;
    const int wm = wid >> 1, wn = wid & 1;     // warp grid 2x2, tile 64x64

    const int xr = tid >> 3, xc = (tid & 7) << 2;   // X: 16 rows/iter, 8 iters
    const int wr = tid >> 5, wc = (tid & 31) << 2;  // W: 4 k-rows/iter, 8 iters

    auto load_tile = [&](int buf, int k0) {
        #pragma unroll
        for (int it = 0; it < 8; it++)
            CP16(&sm.Xs[buf][xr + (it << 4)][xc],
                 &X[(size_t)(m0 + xr + (it << 4)) * DM_ + k0 + xc]);
        #pragma unroll
        for (int it = 0; it < 8; it++)
            CP16(&sm.Ws[buf][wr + (it << 2)][wc],
                 &W[(size_t)(k0 + wr + (it << 2)) * DM_ + n0 + wc]);
    };

    load_tile(0, kbeg);      CP_COMMIT();
    load_tile(1, kbeg + 32); CP_COMMIT();

    float acc[4][8][4] = {};
    int buf = 0;

    for (int kt = 0; kt < kiters; kt++) {
        CP_WAIT1();
        __syncthreads();
        if (kt + 2 < kiters) {
            int nb = buf + 2; if (nb >= 3) nb -= 3;
            load_tile(nb, kbeg + ((kt + 2) << 5));
            CP_COMMIT();
        }

        #pragma unroll
        for (int ks = 0; ks < 4; ks++) {
            int kk = ks << 3;
            float a[4][4], b[8][2];
            #pragma unroll
            for (int mf = 0; mf < 4; mf++) {
                int r = (wm << 6) + (mf << 4) + qd;
                a[mf][0] = sm.Xs[buf][r][kk + lr];
                a[mf][1] = sm.Xs[buf][r + 8][kk + lr];
                a[mf][2] = sm.Xs[buf][r][kk + lr + 4];
                a[mf][3] = sm.Xs[buf][r + 8][kk + lr + 4];
            }
            #pragma unroll
            for (int nf = 0; nf < 8; nf++) {
                int n = (wn << 6) + (nf << 3) + qd;
                b[nf][0] = sm.Ws[buf][kk + lr][n];
                b[nf][1] = sm.Ws[buf][kk + lr + 4][n];
            }
            #pragma unroll
            for (int mf = 0; mf < 4; mf++)
                #pragma unroll
                for (int nf = 0; nf < 8; nf++)
                    mma8f(acc[mf][nf], a[mf], b[nf][0], b[nf][1]);
        }
        if (++buf >= 3) buf -= 3;
    }

    #pragma unroll
    for (int mf = 0; mf < 4; mf++) {
        #pragma unroll
        for (int nf = 0; nf < 8; nf++) {
            #pragma unroll
            for (int rp = 0; rp < 2; rp++) {
                int m = m0 + (wm << 6) + (mf << 4) + qd + (rp << 3);
                int n = n0 + (wn << 6) + (nf << 3) + (lr << 1);
                float v0 = acc[mf][nf][(rp << 1)];
                float v1 = acc[mf][nf][(rp << 1) + 1];
                if (mode == 1) {
                    v0 += __ldg(&bias[n]); v1 += __ldg(&bias[n + 1]);
                    int bb = m >> 11, s = m & (S_ - 1);
                    int h = n >> 6, d = n & 63;
                    float2 w = make_float2(f2tff(v0), f2tff(v1));
                    *(float2*)&out[(((bb * H_ + h) * S_) + s) * D_ + d] = w;
                } else if (mode == 0) {
                    v0 += __ldg(&bias[n]); v1 += __ldg(&bias[n + 1]);
                    *(float2*)&out[(size_t)m * DM_ + n] = make_float2(v0, v1);
                } else {
                    *(float2*)&out[(size_t)m * DM_ + n] = make_float2(v0, v1);
                }
            }
        }
    }
}

__global__ __launch_bounds__(128) void gemm_qkv(
    const float* __restrict__ X,
    const float* __restrict__ b0, const float* __restrict__ b1, const float* __restrict__ b2,
    float* __restrict__ o0, float* __restrict__ o1, float* __restrict__ o2)
{
    extern __shared__ char graw[];
    GSmem& sm = *reinterpret_cast<GSmem*>(graw);
    const int z = blockIdx.z;
    const float* bias = (z == 0) ? b0 : (z == 1) ? b1 : b2;
    float* out = (z == 0) ? o0 : (z == 1) ? o1 : o2;
    gemm_body(sm, X, g_wr[z], bias, out, 1, blockIdx.y << 7, blockIdx.x << 7,
              0, DM_ / 32);
}

// out-projection split-K: z selects K half, writes partial (no bias)
__global__ __launch_bounds__(128) void gemm_out_part(const float* __restrict__ X)
{
    extern __shared__ char graw[];
    GSmem& sm = *reinterpret_cast<GSmem*>(graw);
    const int z = blockIdx.z;
    gemm_body(sm, X, g_wr[3], nullptr, g_part[z], 2,
              blockIdx.y << 7, blockIdx.x << 7, z << 9, 16);
}

__global__ void reduce_out(const float* __restrict__ bias, float* __restrict__ out)
{
    const float4* p0 = (const float4*)g_part[0];
    const float4* p1 = (const float4*)g_part[1];
    float4* o4 = (float4*)out;
    for (int i = blockIdx.x * blockDim.x + threadIdx.x; i < 1048576;
         i += gridDim.x * blockDim.x) {
        int n = (i << 2) & (DM_ - 1);
        float4 a = p0[i], b = p1[i];
        float4 v;
        v.x = a.x + b.x + __ldg(&bias[n]);
        v.y = a.y + b.y + __ldg(&bias[n + 1]);
        v.z = a.z + b.z + __ldg(&bias[n + 2]);
        v.w = a.w + b.w + __ldg(&bias[n + 3]);
        o4[i] = v;
    }
}

// ---------------------------------------------------------------------------
// Flash attention: max-free softmax, q-tile 128, m32/warp, k-tile 64
// (double-buffered, two 32-row compute sub-steps), register P-transpose.
// ---------------------------------------------------------------------------
struct ASmem {
    float Ks[2][64][68];
    float Vs[2][64][72];
    float qrelS[128][8];
    float rkS[NB_][64];
    float rvS[NB_][64];
};

__global__ __launch_bounds__(128, 2) void attn_tf32(
    const float* __restrict__ rel_k, const float* __restrict__ rel_v)
{
    extern __shared__ char sraw[];
    ASmem& sm = *reinterpret_cast<ASmem*>(sraw);
    const int tid = threadIdx.x;
    const int lane = tid & 31, wid = tid >> 5;
    const int qd = lane >> 2, lr = lane & 3;
    const bool odd = lr & 1;
    const int src0 = (lane & 28) | (lr >> 1);
    const int src1 = src0 + 2;
    const int q0 = blockIdx.x << 7;
    const int bh = blockIdx.y;
    const float* qptr = g_q + (size_t)bh * S_ * D_;
    const float* kptr = g_k + (size_t)bh * S_ * D_;
    const float* vptr = g_v + (size_t)bh * S_ * D_;

    auto load_kv = [&](int buf, int k0) {
        #pragma unroll
        for (int it = 0; it < 8; it++) {
            int idx = tid + (it << 7);
            int r = idx >> 4, c4 = (idx & 15) << 2;
            CP16(&sm.Ks[buf][r][c4], &kptr[(size_t)(k0 + r) * D_ + c4]);
            CP16(&sm.Vs[buf][r][c4], &vptr[(size_t)(k0 + r) * D_ + c4]);
        }
    };

    load_kv(0, 0);
    CP_COMMIT();

    for (int t = tid; t < NB_ * 64; t += 128) {
        sm.rkS[t >> 6][t & 63] = rel_k[t];
        sm.rvS[t >> 6][t & 63] = rel_v[t];
    }

    const int rw = wid << 5;
    float qf[2][8][4];
    #pragma unroll
    for (int h = 0; h < 2; h++) {
        const float* qr0 = &qptr[(size_t)(q0 + rw + (h << 4) + qd) * D_];
        #pragma unroll
        for (int kf = 0; kf < 8; kf++) {
            qf[h][kf][0] = __ldg(&qr0[(kf << 3) + lr]);
            qf[h][kf][1] = __ldg(&qr0[(size_t)8 * D_ + (kf << 3) + lr]);
            qf[h][kf][2] = __ldg(&qr0[(kf << 3) + lr + 4]);
            qf[h][kf][3] = __ldg(&qr0[(size_t)8 * D_ + (kf << 3) + lr + 4]);
        }
    }
    __syncthreads();

    #pragma unroll
    for (int st = 0; st < 4; st++) {
        int h = st >> 1, rp = st & 1;
        int rloc = rw + (h << 4) + qd + (rp << 3);
        #pragma unroll
        for (int jb = 0; jb < NB_; jb++) {
            float acc = 0.f;
            #pragma unroll
            for (int kf = 0; kf < 8; kf++) {
                acc += qf[h][kf][rp]     * sm.rkS[jb][(kf << 3) + lr];
                acc += qf[h][kf][rp + 2] * sm.rkS[jb][(kf << 3) + lr + 4];
            }
            acc += __shfl_xor_sync(0xffffffffu, acc, 1);
            acc += __shfl_xor_sync(0xffffffffu, acc, 2);
            if (lr == 0) sm.qrelS[rloc][jb] = acc;
        }
    }
    __syncthreads();

    float O0[8][4] = {}, O1[8][4] = {};
    float lS[4] = {}, bsS[4][NB_] = {};
    const int rmin = q0 + rw;

    for (int kt = 0; kt < S_ / 64; kt++) {
        const int cur = kt & 1;
        CP_WAIT0();
        __syncthreads();
        if (kt + 1 < S_ / 64) { load_kv(cur ^ 1, (kt + 1) << 6); CP_COMMIT(); }

        #pragma unroll
        for (int sub = 0; sub < 2; sub++) {
            const int k0 = (kt << 6) + (sub << 5);
            const float (*Kc)[68] = (const float (*)[68])(sm.Ks[cur] + (sub << 5));
            const float (*Vc)[72] = (const float (*)[72])(sm.Vs[cur] + (sub << 5));

            float s0[4][4] = {}, s1[4][4] = {};
            #pragma unroll
            for (int kf = 0; kf < 8; kf++) {
                #pragma unroll
                for (int nf = 0; nf < 4; nf++) {
                    float b0 = Kc[(nf << 3) + qd][(kf << 3) + lr];
                    float b1 = Kc[(nf << 3) + qd][(kf << 3) + lr + 4];
                    mma8f(s0[nf], qf[0][kf], b0, b1);
                    mma8f(s1[nf], qf[1][kf], b0, b1);
                }
            }

            bool mixed = (k0 > rmin - 34) && (k0 < rmin + 34);

            #pragma unroll
            for (int h = 0; h < 2; h++) {
                float (*s)[4] = (h == 0) ? s0 : s1;
                int stA = h << 1, stB = stA + 1;
                int rlA = rw + (h << 4) + qd;
                int rgA = q0 + rlA, rgB = rgA + 8;
                float rsA = 0.f, rsB = 0.f;

                if (!mixed) {
                    const int bkt = (k0 >= rmin + 34) ? 4 : 0;
                    float cA = sm.qrelS[rlA][bkt] * ALPHA_;
                    float cB = sm.qrelS[rlA + 8][bkt] * ALPHA_;
                    #pragma unroll
                    for (int nf = 0; nf < 4; nf++) {
                        float p0 = exp2p(fmaf(s[nf][0], ALPHA_, cA));
                        float p1 = exp2p(fmaf(s[nf][1], ALPHA_, cA));
                        float p2 = exp2p(fmaf(s[nf][2], ALPHA_, cB));
                        float p3 = exp2p(fmaf(s[nf][3], ALPHA_, cB));
                        s[nf][0] = p0; s[nf][1] = p1; s[nf][2] = p2; s[nf][3] = p3;
                        rsA += p0 + p1; rsB += p2 + p3;
                    }
                    lS[stA] += rsA; lS[stB] += rsB;
                    bsS[stA][bkt] += rsA; bsS[stB][bkt] += rsB;
                } else {
                    #pragma unroll
                    for (int nf = 0; nf < 4; nf++) {
                        #pragma unroll
                        for (int e = 0; e < 4; e++) {
                            int kp = k0 + (nf << 3) + (lr << 1) + (e & 1);
                            int rg = (e < 2) ? rgA : rgB;
                            int rl = (e < 2) ? rlA : rlA + 8;
                            int jb = min(max(kp - rg, -2), 2) + 2;
                            float p = exp2p((s[nf][e] + sm.qrelS[rl][jb]) * ALPHA_);
                            s[nf][e] = p;
                            if (e < 2) { rsA += p; bsS[stA][jb] += p; }
                            else       { rsB += p; bsS[stB][jb] += p; }
                        }
                    }
                    lS[stA] += rsA; lS[stB] += rsB;
                }
            }

            #pragma unroll
            for (int j = 0; j < 4; j++) {
                float a0[4], a1[4];
                {
                    float c0 = f2tff(s0[j][0]), c1 = f2tff(s0[j][1]);
                    float c2 = f2tff(s0[j][2]), c3 = f2tff(s0[j][3]);
                    float t00 = __shfl_sync(0xffffffffu, c0, src0);
                    float t10 = __shfl_sync(0xffffffffu, c1, src0);
                    float t20 = __shfl_sync(0xffffffffu, c2, src0);
                    float t30 = __shfl_sync(0xffffffffu, c3, src0);
                    float t01 = __shfl_sync(0xffffffffu, c0, src1);
                    float t11 = __shfl_sync(0xffffffffu, c1, src1);
                    float t21 = __shfl_sync(0xffffffffu, c2, src1);
                    float t31 = __shfl_sync(0xffffffffu, c3, src1);
                    a0[0] = odd ? t10 : t00; a0[1] = odd ? t30 : t20;
                    a0[2] = odd ? t11 : t01; a0[3] = odd ? t31 : t21;
                }
                {
                    float c0 = f2tff(s1[j][0]), c1 = f2tff(s1[j][1]);
                    float c2 = f2tff(s1[j][2]), c3 = f2tff(s1[j][3]);
                    float t00 = __shfl_sync(0xffffffffu, c0, src0);
                    float t10 = __shfl_sync(0xffffffffu, c1, src0);
                    float t20 = __shfl_sync(0xffffffffu, c2, src0);
                    float t30 = __shfl_sync(0xffffffffu, c3, src0);
                    float t01 = __shfl_sync(0xffffffffu, c0, src1);
                    float t11 = __shfl_sync(0xffffffffu, c1, src1);
                    float t21 = __shfl_sync(0xffffffffu, c2, src1);
                    float t31 = __shfl_sync(0xffffffffu, c3, src1);
                    a1[0] = odd ? t10 : t00; a1[1] = odd ? t30 : t20;
                    a1[2] = odd ? t11 : t01; a1[3] = odd ? t31 : t21;
                }
                #pragma unroll
                for (int nf = 0; nf < 8; nf++) {
                    float b0 = Vc[(j << 3) + lr][(nf << 3) + qd];
                    float b1 = Vc[(j << 3) + lr + 4][(nf << 3) + qd];
                    mma8f(O0[nf], a0, b0, b1);
                    mma8f(O1[nf], a1, b0, b1);
                }
            }
        }
    }

    #pragma unroll
    for (int st = 0; st < 4; st++) {
        #pragma unroll
        for (int o = 1; o <= 2; o <<= 1) {
            lS[st] += __shfl_xor_sync(0xffffffffu, lS[st], o);
            #pragma unroll
            for (int jb = 0; jb < NB_; jb++)
                bsS[st][jb] += __shfl_xor_sync(0xffffffffu, bsS[st][jb], o);
        }
    }

    const int bb = bh / H_, hh = bh % H_;
    #pragma unroll
    for (int h = 0; h < 2; h++) {
        float (*Oh)[4] = (h == 0) ? O0 : O1;
        #pragma unroll
        for (int rp = 0; rp < 2; rp++) {
            int st = (h << 1) + rp;
            float inv = 1.f / lS[st];
            int rg = q0 + rw + (h << 4) + qd + (rp << 3);
            #pragma unroll
            for (int nf = 0; nf < 8; nf++) {
                int d0 = (nf << 3) + (lr << 1);
                float o2a = 0.f, o2b = 0.f;
                #pragma unroll
                for (int jb = 0; jb < NB_; jb++) {
                    o2a += bsS[st][jb] * sm.rvS[jb][d0];
                    o2b += bsS[st][jb] * sm.rvS[jb][d0 + 1];
                }
                float2 w = make_float2(f2tff((Oh[nf][(rp << 1)] + o2a) * inv),
                                       f2tff((Oh[nf][(rp << 1) + 1] + o2b) * inv));
                *(float2*)&g_att[(((size_t)bb * S_ + rg) * H_ + hh) * D_ + d0] = w;
            }
        }
    }
}

// ---------------------------------------------------------------------------
extern "C" void kernel_launch(void* const* d_in, const int* in_sizes, int n_in,
                              void* d_out, int out_size) {
    const float* x    = (const float*)d_in[0];
    const float* Wq   = (const float*)d_in[1];
    const float* bq   = (const float*)d_in[2];
    const float* Wk   = (const float*)d_in[3];
    const float* bk   = (const float*)d_in[4];
    const float* Wv   = (const float*)d_in[5];
    const float* bv   = (const float*)d_in[6];
    const float* Wo   = (const float*)d_in[7];
    const float* bo   = (const float*)d_in[8];
    const float* relk = (const float*)d_in[9];
    const float* relv = (const float*)d_in[10];
    float* out = (float*)d_out;

    float *gq, *gk, *gv, *gatt, *gxr;
    cudaGetSymbolAddress((void**)&gq,   g_q);
    cudaGetSymbolAddress((void**)&gk,   g_k);
    cudaGetSymbolAddress((void**)&gv,   g_v);
    cudaGetSymbolAddress((void**)&gatt, g_att);
    cudaGetSymbolAddress((void**)&gxr,  g_xr);

    cudaFuncSetAttribute(gemm_qkv, cudaFuncAttributeMaxDynamicSharedMemorySize,
                         (int)sizeof(GSmem));
    cudaFuncSetAttribute(gemm_out_part, cudaFuncAttributeMaxDynamicSharedMemorySize,
                         (int)sizeof(GSmem));
    cudaFuncSetAttribute(attn_tf32, cudaFuncAttributeMaxDynamicSharedMemorySize,
                         (int)sizeof(ASmem));

    round_pass<<<2048, 256>>>(x, Wq, Wk, Wv, Wo);

    gemm_qkv<<<dim3(DM_ / 128, (B_ * S_) / 128, 3), 128, sizeof(GSmem)>>>(
        gxr, bq, bk, bv, gq, gk, gv);
    attn_tf32<<<dim3(S_ / 128, B_ * H_), 128, sizeof(ASmem)>>>(relk, relv);
    gemm_out_part<<<dim3(DM_ / 128, (B_ * S_) / 128, 2), 128, sizeof(GSmem)>>>(gatt);
    reduce_out<<<2048, 256>>>(bo, out);
}

// round 16
// speedup vs baseline: 1.0310x; 1.0310x over previous
#include <cuda_runtime.h>
#include <cstdint>

#define B_   2
#define S_   2048
#define DM_  1024
#define H_   16
#define D_   64
#define NB_  5
#define SCALE_ 0.125f
#define LOG2E_ 1.4426950408889634f
#define ALPHA_ (SCALE_ * LOG2E_)

// Static device scratch
__device__ float g_q[B_*H_*S_*D_];
__device__ float g_k[B_*H_*S_*D_];
__device__ float g_v[B_*H_*S_*D_];
__device__ float g_att[B_*S_*DM_];

// ---------------------------------------------------------------------------
__device__ __forceinline__ unsigned f2tf(float x) {
    unsigned r;
    asm("cvt.rna.tf32.f32 %0, %1;" : "=r"(r) : "f"(x));
    return r;
}
__device__ __forceinline__ float f2tff(float x) { return __uint_as_float(f2tf(x)); }

__device__ __forceinline__ void mma8f(float* c, const float* a, float b0f, float b1f) {
    asm volatile(
        "mma.sync.aligned.m16n8k8.row.col.f32.tf32.tf32.f32 "
        "{%0,%1,%2,%3}, {%4,%5,%6,%7}, {%8,%9}, {%0,%1,%2,%3};"
        : "+f"(c[0]), "+f"(c[1]), "+f"(c[2]), "+f"(c[3])
        : "r"(__float_as_uint(a[0])), "r"(__float_as_uint(a[1])),
          "r"(__float_as_uint(a[2])), "r"(__float_as_uint(a[3])),
          "r"(__float_as_uint(b0f)), "r"(__float_as_uint(b1f)));
}

#define CP16(dst_smem, src) \
    asm volatile("cp.async.cg.shared.global [%0], [%1], 16;\n" :: \
        "r"((unsigned)__cvta_generic_to_shared(dst_smem)), "l"(src) : "memory")
#define CP_COMMIT() asm volatile("cp.async.commit_group;\n" ::: "memory")
#define CP_WAIT0()  asm volatile("cp.async.wait_group 0;\n" ::: "memory")
#define CP_WAIT1()  asm volatile("cp.async.wait_group 1;\n" ::: "memory")

// exp2 on FMA pipe, max-free softmax domain; clamps low at -60.
__device__ __forceinline__ float exp2p(float y) {
    y = fmaxf(y, -60.f);
    float t = y + 12582912.0f;           // 1.5*2^23 round-to-nearest
    float fl = t - 12582912.0f;
    float f = y - fl;                    // [-0.5, 0.5]
    float p = fmaf(1.5403530e-4f, f, 1.3333558e-3f);
    p = fmaf(p, f, 9.6181291e-3f);
    p = fmaf(p, f, 5.5504109e-2f);
    p = fmaf(p, f, 2.4022651e-1f);
    p = fmaf(p, f, 6.9314718e-1f);
    p = fmaf(p, f, 1.0f);
    int e = ((__float_as_int(t) & 0x7FFFFF) - 0x400000 + 127) << 23;
    return p * __int_as_float(e);
}

// ---------------------------------------------------------------------------
// TF32 GEMM: block 128x128, 128 threads (4 warps, warp tile 64x64),
// k-step 32, 3-stage cp.async. Rounding applied to fragments after LDS
// (no pre-pass needed; raw fp32 inputs).
// ---------------------------------------------------------------------------
struct GSmem {
    float Xs[3][128][36];
    float Ws[3][32][132];
};

__device__ __forceinline__ void gemm_body(
    GSmem& sm, const float* __restrict__ X, const float* __restrict__ W,
    const float* __restrict__ bias, float* __restrict__ out, int permute,
    int m0, int n0)
{
    const int tid  = threadIdx.x;
    const int lane = tid & 31, wid = tid >> 5;
    const int qd = lane >> 2, lr = lane & 3;
    const int wm = wid >> 1, wn = wid & 1;     // warp grid 2x2, tile 64x64

    const int xr = tid >> 3, xc = (tid & 7) << 2;   // X: 16 rows/iter, 8 iters
    const int wr = tid >> 5, wc = (tid & 31) << 2;  // W: 4 k-rows/iter, 8 iters

    auto load_tile = [&](int buf, int k0) {
        #pragma unroll
        for (int it = 0; it < 8; it++)
            CP16(&sm.Xs[buf][xr + (it << 4)][xc],
                 &X[(size_t)(m0 + xr + (it << 4)) * DM_ + k0 + xc]);
        #pragma unroll
        for (int it = 0; it < 8; it++)
            CP16(&sm.Ws[buf][wr + (it << 2)][wc],
                 &W[(size_t)(k0 + wr + (it << 2)) * DM_ + n0 + wc]);
    };

    load_tile(0, 0);  CP_COMMIT();
    load_tile(1, 32); CP_COMMIT();

    float acc[4][8][4] = {};
    int buf = 0;

    for (int kt = 0; kt < DM_ / 32; kt++) {
        CP_WAIT1();
        __syncthreads();
        if (kt + 2 < DM_ / 32) {
            int nb = buf + 2; if (nb >= 3) nb -= 3;
            load_tile(nb, (kt + 2) << 5);
            CP_COMMIT();
        }

        #pragma unroll
        for (int ks = 0; ks < 4; ks++) {
            int kk = ks << 3;
            float a[4][4], b[8][2];
            #pragma unroll
            for (int mf = 0; mf < 4; mf++) {
                int r = (wm << 6) + (mf << 4) + qd;
                a[mf][0] = f2tff(sm.Xs[buf][r][kk + lr]);
                a[mf][1] = f2tff(sm.Xs[buf][r + 8][kk + lr]);
                a[mf][2] = f2tff(sm.Xs[buf][r][kk + lr + 4]);
                a[mf][3] = f2tff(sm.Xs[buf][r + 8][kk + lr + 4]);
            }
            #pragma unroll
            for (int nf = 0; nf < 8; nf++) {
                int n = (wn << 6) + (nf << 3) + qd;
                b[nf][0] = f2tff(sm.Ws[buf][kk + lr][n]);
                b[nf][1] = f2tff(sm.Ws[buf][kk + lr + 4][n]);
            }
            #pragma unroll
            for (int mf = 0; mf < 4; mf++)
                #pragma unroll
                for (int nf = 0; nf < 8; nf++)
                    mma8f(acc[mf][nf], a[mf], b[nf][0], b[nf][1]);
        }
        if (++buf >= 3) buf -= 3;
    }

    #pragma unroll
    for (int mf = 0; mf < 4; mf++) {
        #pragma unroll
        for (int nf = 0; nf < 8; nf++) {
            #pragma unroll
            for (int rp = 0; rp < 2; rp++) {
                int m = m0 + (wm << 6) + (mf << 4) + qd + (rp << 3);
                int n = n0 + (wn << 6) + (nf << 3) + (lr << 1);
                float v0 = acc[mf][nf][(rp << 1)]     + __ldg(&bias[n]);
                float v1 = acc[mf][nf][(rp << 1) + 1] + __ldg(&bias[n + 1]);
                if (permute) {
                    int bb = m >> 11, s = m & (S_ - 1);
                    int h = n >> 6, d = n & 63;
                    float2 w = make_float2(f2tff(v0), f2tff(v1));
                    *(float2*)&out[(((bb * H_ + h) * S_) + s) * D_ + d] = w;
                } else {
                    *(float2*)&out[(size_t)m * DM_ + n] = make_float2(v0, v1);
                }
            }
        }
    }
}

__global__ __launch_bounds__(128) void gemm_qkv(
    const float* __restrict__ X,
    const float* __restrict__ W0, const float* __restrict__ W1, const float* __restrict__ W2,
    const float* __restrict__ b0, const float* __restrict__ b1, const float* __restrict__ b2,
    float* __restrict__ o0, float* __restrict__ o1, float* __restrict__ o2)
{
    extern __shared__ char graw[];
    GSmem& sm = *reinterpret_cast<GSmem*>(graw);
    const int z = blockIdx.z;
    const float* W = (z == 0) ? W0 : (z == 1) ? W1 : W2;
    const float* bias = (z == 0) ? b0 : (z == 1) ? b1 : b2;
    float* out = (z == 0) ? o0 : (z == 1) ? o1 : o2;
    gemm_body(sm, X, W, bias, out, 1, blockIdx.y << 7, blockIdx.x << 7);
}

__global__ __launch_bounds__(128) void gemm_out(
    const float* __restrict__ X, const float* __restrict__ W,
    const float* __restrict__ bias, float* __restrict__ out)
{
    extern __shared__ char graw[];
    GSmem& sm = *reinterpret_cast<GSmem*>(graw);
    gemm_body(sm, X, W, bias, out, 0, blockIdx.y << 7, blockIdx.x << 7);
}

// ---------------------------------------------------------------------------
// Flash attention (R14/R11 config): max-free softmax, q-tile 128, m32/warp,
// k-tile 32, cp.async DB, register shuffle-transpose for P.
// ---------------------------------------------------------------------------
struct ASmem {
    float Ks[2][32][68];
    float Vs[2][32][72];
    float qrelS[128][8];
    float rkS[NB_][64];
    float rvS[NB_][64];
};

__global__ __launch_bounds__(128, 2) void attn_tf32(
    const float* __restrict__ rel_k, const float* __restrict__ rel_v)
{
    extern __shared__ char sraw[];
    ASmem& sm = *reinterpret_cast<ASmem*>(sraw);
    const int tid = threadIdx.x;
    const int lane = tid & 31, wid = tid >> 5;
    const int qd = lane >> 2, lr = lane & 3;
    const bool odd = lr & 1;
    const int src0 = (lane & 28) | (lr >> 1);
    const int src1 = src0 + 2;
    const int q0 = blockIdx.x << 7;
    const int bh = blockIdx.y;
    const float* qptr = g_q + (size_t)bh * S_ * D_;
    const float* kptr = g_k + (size_t)bh * S_ * D_;
    const float* vptr = g_v + (size_t)bh * S_ * D_;

    auto load_kv = [&](int buf, int k0) {
        #pragma unroll
        for (int it = 0; it < 4; it++) {
            int idx = tid + (it << 7);
            int r = idx >> 4, c4 = (idx & 15) << 2;
            CP16(&sm.Ks[buf][r][c4], &kptr[(size_t)(k0 + r) * D_ + c4]);
            CP16(&sm.Vs[buf][r][c4], &vptr[(size_t)(k0 + r) * D_ + c4]);
        }
    };

    load_kv(0, 0);
    CP_COMMIT();

    for (int t = tid; t < NB_ * 64; t += 128) {
        sm.rkS[t >> 6][t & 63] = rel_k[t];
        sm.rvS[t >> 6][t & 63] = rel_v[t];
    }

    const int rw = wid << 5;
    float qf[2][8][4];
    #pragma unroll
    for (int h = 0; h < 2; h++) {
        const float* qr0 = &qptr[(size_t)(q0 + rw + (h << 4) + qd) * D_];
        #pragma unroll
        for (int kf = 0; kf < 8; kf++) {
            qf[h][kf][0] = __ldg(&qr0[(kf << 3) + lr]);
            qf[h][kf][1] = __ldg(&qr0[(size_t)8 * D_ + (kf << 3) + lr]);
            qf[h][kf][2] = __ldg(&qr0[(kf << 3) + lr + 4]);
            qf[h][kf][3] = __ldg(&qr0[(size_t)8 * D_ + (kf << 3) + lr + 4]);
        }
    }
    __syncthreads();

    #pragma unroll
    for (int st = 0; st < 4; st++) {
        int h = st >> 1, rp = st & 1;
        int rloc = rw + (h << 4) + qd + (rp << 3);
        #pragma unroll
        for (int jb = 0; jb < NB_; jb++) {
            float acc = 0.f;
            #pragma unroll
            for (int kf = 0; kf < 8; kf++) {
                acc += qf[h][kf][rp]     * sm.rkS[jb][(kf << 3) + lr];
                acc += qf[h][kf][rp + 2] * sm.rkS[jb][(kf << 3) + lr + 4];
            }
            acc += __shfl_xor_sync(0xffffffffu, acc, 1);
            acc += __shfl_xor_sync(0xffffffffu, acc, 2);
            if (lr == 0) sm.qrelS[rloc][jb] = acc;
        }
    }
    __syncthreads();

    float O0[8][4] = {}, O1[8][4] = {};
    float lS[4] = {}, bsS[4][NB_] = {};
    const int rmin = q0 + rw;

    for (int kt = 0; kt < S_ / 32; kt++) {
        const int k0 = kt << 5;
        const int cur = kt & 1;
        CP_WAIT0();
        __syncthreads();
        if (kt + 1 < S_ / 32) { load_kv(cur ^ 1, k0 + 32); CP_COMMIT(); }

        const float (*Kc)[68] = sm.Ks[cur];
        const float (*Vc)[72] = sm.Vs[cur];

        float s0[4][4] = {}, s1[4][4] = {};
        #pragma unroll
        for (int kf = 0; kf < 8; kf++) {
            #pragma unroll
            for (int nf = 0; nf < 4; nf++) {
                float b0 = Kc[(nf << 3) + qd][(kf << 3) + lr];
                float b1 = Kc[(nf << 3) + qd][(kf << 3) + lr + 4];
                mma8f(s0[nf], qf[0][kf], b0, b1);
                mma8f(s1[nf], qf[1][kf], b0, b1);
            }
        }

        bool mixed = (k0 > rmin - 34) && (k0 < rmin + 34);

        #pragma unroll
        for (int h = 0; h < 2; h++) {
            float (*s)[4] = (h == 0) ? s0 : s1;
            int stA = h << 1, stB = stA + 1;
            int rlA = rw + (h << 4) + qd;
            int rgA = q0 + rlA, rgB = rgA + 8;
            float rsA = 0.f, rsB = 0.f;

            if (!mixed) {
                const int bkt = (k0 >= rmin + 34) ? 4 : 0;
                float cA = sm.qrelS[rlA][bkt] * ALPHA_;
                float cB = sm.qrelS[rlA + 8][bkt] * ALPHA_;
                #pragma unroll
                for (int nf = 0; nf < 4; nf++) {
                    float p0 = exp2p(fmaf(s[nf][0], ALPHA_, cA));
                    float p1 = exp2p(fmaf(s[nf][1], ALPHA_, cA));
                    float p2 = exp2p(fmaf(s[nf][2], ALPHA_, cB));
                    float p3 = exp2p(fmaf(s[nf][3], ALPHA_, cB));
                    s[nf][0] = p0; s[nf][1] = p1; s[nf][2] = p2; s[nf][3] = p3;
                    rsA += p0 + p1; rsB += p2 + p3;
                }
                lS[stA] += rsA; lS[stB] += rsB;
                bsS[stA][bkt] += rsA; bsS[stB][bkt] += rsB;
            } else {
                #pragma unroll
                for (int nf = 0; nf < 4; nf++) {
                    #pragma unroll
                    for (int e = 0; e < 4; e++) {
                        int kp = k0 + (nf << 3) + (lr << 1) + (e & 1);
                        int rg = (e < 2) ? rgA : rgB;
                        int rl = (e < 2) ? rlA : rlA + 8;
                        int jb = min(max(kp - rg, -2), 2) + 2;
                        float p = exp2p((s[nf][e] + sm.qrelS[rl][jb]) * ALPHA_);
                        s[nf][e] = p;
                        if (e < 2) { rsA += p; bsS[stA][jb] += p; }
                        else       { rsB += p; bsS[stB][jb] += p; }
                    }
                }
                lS[stA] += rsA; lS[stB] += rsB;
            }
        }

        #pragma unroll
        for (int j = 0; j < 4; j++) {
            float a0[4], a1[4];
            {
                float c0 = f2tff(s0[j][0]), c1 = f2tff(s0[j][1]);
                float c2 = f2tff(s0[j][2]), c3 = f2tff(s0[j][3]);
                float t00 = __shfl_sync(0xffffffffu, c0, src0);
                float t10 = __shfl_sync(0xffffffffu, c1, src0);
                float t20 = __shfl_sync(0xffffffffu, c2, src0);
                float t30 = __shfl_sync(0xffffffffu, c3, src0);
                float t01 = __shfl_sync(0xffffffffu, c0, src1);
                float t11 = __shfl_sync(0xffffffffu, c1, src1);
                float t21 = __shfl_sync(0xffffffffu, c2, src1);
                float t31 = __shfl_sync(0xffffffffu, c3, src1);
                a0[0] = odd ? t10 : t00; a0[1] = odd ? t30 : t20;
                a0[2] = odd ? t11 : t01; a0[3] = odd ? t31 : t21;
            }
            {
                float c0 = f2tff(s1[j][0]), c1 = f2tff(s1[j][1]);
                float c2 = f2tff(s1[j][2]), c3 = f2tff(s1[j][3]);
                float t00 = __shfl_sync(0xffffffffu, c0, src0);
                float t10 = __shfl_sync(0xffffffffu, c1, src0);
                float t20 = __shfl_sync(0xffffffffu, c2, src0);
                float t30 = __shfl_sync(0xffffffffu, c3, src0);
                float t01 = __shfl_sync(0xffffffffu, c0, src1);
                float t11 = __shfl_sync(0xffffffffu, c1, src1);
                float t21 = __shfl_sync(0xffffffffu, c2, src1);
                float t31 = __shfl_sync(0xffffffffu, c3, src1);
                a1[0] = odd ? t10 : t00; a1[1] = odd ? t30 : t20;
                a1[2] = odd ? t11 : t01; a1[3] = odd ? t31 : t21;
            }
            #pragma unroll
            for (int nf = 0; nf < 8; nf++) {
                float b0 = Vc[(j << 3) + lr][(nf << 3) + qd];
                float b1 = Vc[(j << 3) + lr + 4][(nf << 3) + qd];
                mma8f(O0[nf], a0, b0, b1);
                mma8f(O1[nf], a1, b0, b1);
            }
        }
    }

    #pragma unroll
    for (int st = 0; st < 4; st++) {
        #pragma unroll
        for (int o = 1; o <= 2; o <<= 1) {
            lS[st] += __shfl_xor_sync(0xffffffffu, lS[st], o);
            #pragma unroll
            for (int jb = 0; jb < NB_; jb++)
                bsS[st][jb] += __shfl_xor_sync(0xffffffffu, bsS[st][jb], o);
        }
    }

    const int bb = bh / H_, hh = bh % H_;
    #pragma unroll
    for (int h = 0; h < 2; h++) {
        float (*Oh)[4] = (h == 0) ? O0 : O1;
        #pragma unroll
        for (int rp = 0; rp < 2; rp++) {
            int st = (h << 1) + rp;
            float inv = 1.f / lS[st];
            int rg = q0 + rw + (h << 4) + qd + (rp << 3);
            #pragma unroll
            for (int nf = 0; nf < 8; nf++) {
                int d0 = (nf << 3) + (lr << 1);
                float o2a = 0.f, o2b = 0.f;
                #pragma unroll
                for (int jb = 0; jb < NB_; jb++) {
                    o2a += bsS[st][jb] * sm.rvS[jb][d0];
                    o2b += bsS[st][jb] * sm.rvS[jb][d0 + 1];
                }
                float2 w = make_float2(f2tff((Oh[nf][(rp << 1)] + o2a) * inv),
                                       f2tff((Oh[nf][(rp << 1) + 1] + o2b) * inv));
                *(float2*)&g_att[(((size_t)bb * S_ + rg) * H_ + hh) * D_ + d0] = w;
            }
        }
    }
}

// ---------------------------------------------------------------------------
extern "C" void kernel_launch(void* const* d_in, const int* in_sizes, int n_in,
                              void* d_out, int out_size) {
    const float* x    = (const float*)d_in[0];
    const float* Wq   = (const float*)d_in[1];
    const float* bq   = (const float*)d_in[2];
    const float* Wk   = (const float*)d_in[3];
    const float* bk   = (const float*)d_in[4];
    const float* Wv   = (const float*)d_in[5];
    const float* bv   = (const float*)d_in[6];
    const float* Wo   = (const float*)d_in[7];
    const float* bo   = (const float*)d_in[8];
    const float* relk = (const float*)d_in[9];
    const float* relv = (const float*)d_in[10];
    float* out = (float*)d_out;

    float *gq, *gk, *gv, *gatt;
    cudaGetSymbolAddress((void**)&gq,   g_q);
    cudaGetSymbolAddress((void**)&gk,   g_k);
    cudaGetSymbolAddress((void**)&gv,   g_v);
    cudaGetSymbolAddress((void**)&gatt, g_att);

    cudaFuncSetAttribute(gemm_qkv, cudaFuncAttributeMaxDynamicSharedMemorySize,
                         (int)sizeof(GSmem));
    cudaFuncSetAttribute(gemm_out, cudaFuncAttributeMaxDynamicSharedMemorySize,
                         (int)sizeof(GSmem));
    cudaFuncSetAttribute(attn_tf32, cudaFuncAttributeMaxDynamicSharedMemorySize,
                         (int)sizeof(ASmem));

    gemm_qkv<<<dim3(DM_ / 128, (B_ * S_) / 128, 3), 128, sizeof(GSmem)>>>(
        x, Wq, Wk, Wv, bq, bk, bv, gq, gk, gv);
    attn_tf32<<<dim3(S_ / 128, B_ * H_), 128, sizeof(ASmem)>>>(relk, relv);
    gemm_out<<<dim3(DM_ / 128, (B_ * S_) / 128), 128, sizeof(GSmem)>>>(gatt, Wo, bo, out);
}

// round 17
// speedup vs baseline: 1.0831x; 1.0506x over previous
#include <cuda_runtime.h>
#include <cstdint>

#define B_   2
#define S_   2048
#define DM_  1024
#define H_   16
#define D_   64
#define NB_  5
#define SCALE_ 0.125f
#define LOG2E_ 1.4426950408889634f
#define ALPHA_ (SCALE_ * LOG2E_)

// Static device scratch
__device__ float g_q[B_*H_*S_*D_];
__device__ float g_k[B_*H_*S_*D_];
__device__ float g_v[B_*H_*S_*D_];
__device__ float g_att[B_*S_*DM_];
__device__ float g_xr[4096*1024];
__device__ float g_wr[4][1024*1024];   // tf32-rounded W (k-major)

// ---------------------------------------------------------------------------
__device__ __forceinline__ unsigned f2tf(float x) {
    unsigned r;
    asm("cvt.rna.tf32.f32 %0, %1;" : "=r"(r) : "f"(x));
    return r;
}
__device__ __forceinline__ float f2tff(float x) { return __uint_as_float(f2tf(x)); }

__device__ __forceinline__ void mma8f(float* c, const float* a, float b0f, float b1f) {
    asm volatile(
        "mma.sync.aligned.m16n8k8.row.col.f32.tf32.tf32.f32 "
        "{%0,%1,%2,%3}, {%4,%5,%6,%7}, {%8,%9}, {%0,%1,%2,%3};"
        : "+f"(c[0]), "+f"(c[1]), "+f"(c[2]), "+f"(c[3])
        : "r"(__float_as_uint(a[0])), "r"(__float_as_uint(a[1])),
          "r"(__float_as_uint(a[2])), "r"(__float_as_uint(a[3])),
          "r"(__float_as_uint(b0f)), "r"(__float_as_uint(b1f)));
}

#define CP16(dst_smem, src) \
    asm volatile("cp.async.cg.shared.global [%0], [%1], 16;\n" :: \
        "r"((unsigned)__cvta_generic_to_shared(dst_smem)), "l"(src) : "memory")
#define CP_COMMIT() asm volatile("cp.async.commit_group;\n" ::: "memory")
#define CP_WAIT0()  asm volatile("cp.async.wait_group 0;\n" ::: "memory")
#define CP_WAIT1()  asm volatile("cp.async.wait_group 1;\n" ::: "memory")

// exp2 on FMA pipe, max-free softmax domain; clamps low at -60.
// Degree-4 poly on [-0.5, 0.5]: max rel error ~4.5e-5 (<< tf32 noise 4e-4).
__device__ __forceinline__ float exp2p(float y) {
    y = fmaxf(y, -60.f);
    float t = y + 12582912.0f;           // 1.5*2^23 round-to-nearest
    float fl = t - 12582912.0f;
    float f = y - fl;                    // [-0.5, 0.5]
    float p = fmaf(9.6181291e-3f, f, 5.5504109e-2f);
    p = fmaf(p, f, 2.4022651e-1f);
    p = fmaf(p, f, 6.9314718e-1f);
    p = fmaf(p, f, 1.0f);
    int e = ((__float_as_int(t) & 0x7FFFFF) - 0x400000 + 127) << 23;
    return p * __int_as_float(e);
}

// ---------------------------------------------------------------------------
// Pre-pass: tf32-round x and the 4 weight matrices.
// ---------------------------------------------------------------------------
__global__ void round_pass(const float* __restrict__ x,  const float* __restrict__ wq,
                           const float* __restrict__ wk, const float* __restrict__ wv,
                           const float* __restrict__ wo)
{
    const int total = 1048576 + 4 * 262144;
    for (int i = blockIdx.x * blockDim.x + threadIdx.x; i < total;
         i += gridDim.x * blockDim.x) {
        const float4* src; float4* dst; int off;
        if (i < 1048576) { src = (const float4*)x; dst = (float4*)g_xr; off = i; }
        else {
            int j = i - 1048576; int seg = j >> 18; off = j & 262143;
            const float* s4 = (seg == 0) ? wq : (seg == 1) ? wk : (seg == 2) ? wv : wo;
            src = (const float4*)s4; dst = (float4*)g_wr[seg];
        }
        float4 v = src[off];
        v.x = f2tff(v.x); v.y = f2tff(v.y); v.z = f2tff(v.z); v.w = f2tff(v.w);
        dst[off] = v;
    }
}

// ---------------------------------------------------------------------------
// TF32 GEMM: block 128x128, 128 threads (4 warps, warp tile 64x64),
// k-step 32, 3-stage cp.async. Inputs pre-rounded.
// ---------------------------------------------------------------------------
struct GSmem {
    float Xs[3][128][36];
    float Ws[3][32][132];
};

__device__ __forceinline__ void gemm_body(
    GSmem& sm, const float* __restrict__ X, const float* __restrict__ W,
    const float* __restrict__ bias, float* __restrict__ out, int permute,
    int m0, int n0)
{
    const int tid  = threadIdx.x;
    const int lane = tid & 31, wid = tid >> 5;
    const int qd = lane >> 2, lr = lane & 3;
    const int wm = wid >> 1, wn = wid & 1;     // warp grid 2x2, tile 64x64

    const int xr = tid >> 3, xc = (tid & 7) << 2;   // X: 16 rows/iter, 8 iters
    const int wr = tid >> 5, wc = (tid & 31) << 2;  // W: 4 k-rows/iter, 8 iters

    auto load_tile = [&](int buf, int k0) {
        #pragma unroll
        for (int it = 0; it < 8; it++)
            CP16(&sm.Xs[buf][xr + (it << 4)][xc],
                 &X[(size_t)(m0 + xr + (it << 4)) * DM_ + k0 + xc]);
        #pragma unroll
        for (int it = 0; it < 8; it++)
            CP16(&sm.Ws[buf][wr + (it << 2)][wc],
                 &W[(size_t)(k0 + wr + (it << 2)) * DM_ + n0 + wc]);
    };

    load_tile(0, 0);  CP_COMMIT();
    load_tile(1, 32); CP_COMMIT();

    float acc[4][8][4] = {};
    int buf = 0;

    for (int kt = 0; kt < DM_ / 32; kt++) {
        CP_WAIT1();
        __syncthreads();
        if (kt + 2 < DM_ / 32) {
            int nb = buf + 2; if (nb >= 3) nb -= 3;
            load_tile(nb, (kt + 2) << 5);
            CP_COMMIT();
        }

        #pragma unroll
        for (int ks = 0; ks < 4; ks++) {
            int kk = ks << 3;
            float a[4][4], b[8][2];
            #pragma unroll
            for (int mf = 0; mf < 4; mf++) {
                int r = (wm << 6) + (mf << 4) + qd;
                a[mf][0] = sm.Xs[buf][r][kk + lr];
                a[mf][1] = sm.Xs[buf][r + 8][kk + lr];
                a[mf][2] = sm.Xs[buf][r][kk + lr + 4];
                a[mf][3] = sm.Xs[buf][r + 8][kk + lr + 4];
            }
            #pragma unroll
            for (int nf = 0; nf < 8; nf++) {
                int n = (wn << 6) + (nf << 3) + qd;
                b[nf][0] = sm.Ws[buf][kk + lr][n];
                b[nf][1] = sm.Ws[buf][kk + lr + 4][n];
            }
            #pragma unroll
            for (int mf = 0; mf < 4; mf++)
                #pragma unroll
                for (int nf = 0; nf < 8; nf++)
                    mma8f(acc[mf][nf], a[mf], b[nf][0], b[nf][1]);
        }
        if (++buf >= 3) buf -= 3;
    }

    #pragma unroll
    for (int mf = 0; mf < 4; mf++) {
        #pragma unroll
        for (int nf = 0; nf < 8; nf++) {
            #pragma unroll
            for (int rp = 0; rp < 2; rp++) {
                int m = m0 + (wm << 6) + (mf << 4) + qd + (rp << 3);
                int n = n0 + (wn << 6) + (nf << 3) + (lr << 1);
                float v0 = acc[mf][nf][(rp << 1)]     + __ldg(&bias[n]);
                float v1 = acc[mf][nf][(rp << 1) + 1] + __ldg(&bias[n + 1]);
                if (permute) {
                    int bb = m >> 11, s = m & (S_ - 1);
                    int h = n >> 6, d = n & 63;
                    float2 w = make_float2(f2tff(v0), f2tff(v1));
                    *(float2*)&out[(((bb * H_ + h) * S_) + s) * D_ + d] = w;
                } else {
                    *(float2*)&out[(size_t)m * DM_ + n] = make_float2(v0, v1);
                }
            }
        }
    }
}

__global__ __launch_bounds__(128) void gemm_qkv(
    const float* __restrict__ X,
    const float* __restrict__ b0, const float* __restrict__ b1, const float* __restrict__ b2,
    float* __restrict__ o0, float* __restrict__ o1, float* __restrict__ o2)
{
    extern __shared__ char graw[];
    GSmem& sm = *reinterpret_cast<GSmem*>(graw);
    const int z = blockIdx.z;
    const float* bias = (z == 0) ? b0 : (z == 1) ? b1 : b2;
    float* out = (z == 0) ? o0 : (z == 1) ? o1 : o2;
    gemm_body(sm, X, g_wr[z], bias, out, 1, blockIdx.y << 7, blockIdx.x << 7);
}

__global__ __launch_bounds__(128) void gemm_out(
    const float* __restrict__ X, const float* __restrict__ bias, float* __restrict__ out)
{
    extern __shared__ char graw[];
    GSmem& sm = *reinterpret_cast<GSmem*>(graw);
    gemm_body(sm, X, g_wr[3], bias, out, 0, blockIdx.y << 7, blockIdx.x << 7);
}

// ---------------------------------------------------------------------------
// Flash attention: max-free softmax, q-tile 128, m32/warp, k-tile 32,
// cp.async DB, register shuffle-transpose for P.
// ---------------------------------------------------------------------------
struct ASmem {
    float Ks[2][32][68];
    float Vs[2][32][72];
    float qrelS[128][8];
    float rkS[NB_][64];
    float rvS[NB_][64];
};

__global__ __launch_bounds__(128, 2) void attn_tf32(
    const float* __restrict__ rel_k, const float* __restrict__ rel_v)
{
    extern __shared__ char sraw[];
    ASmem& sm = *reinterpret_cast<ASmem*>(sraw);
    const int tid = threadIdx.x;
    const int lane = tid & 31, wid = tid >> 5;
    const int qd = lane >> 2, lr = lane & 3;
    const bool odd = lr & 1;
    const int src0 = (lane & 28) | (lr >> 1);
    const int src1 = src0 + 2;
    const int q0 = blockIdx.x << 7;
    const int bh = blockIdx.y;
    const float* qptr = g_q + (size_t)bh * S_ * D_;
    const float* kptr = g_k + (size_t)bh * S_ * D_;
    const float* vptr = g_v + (size_t)bh * S_ * D_;

    auto load_kv = [&](int buf, int k0) {
        #pragma unroll
        for (int it = 0; it < 4; it++) {
            int idx = tid + (it << 7);
            int r = idx >> 4, c4 = (idx & 15) << 2;
            CP16(&sm.Ks[buf][r][c4], &kptr[(size_t)(k0 + r) * D_ + c4]);
            CP16(&sm.Vs[buf][r][c4], &vptr[(size_t)(k0 + r) * D_ + c4]);
        }
    };

    load_kv(0, 0);
    CP_COMMIT();

    for (int t = tid; t < NB_ * 64; t += 128) {
        sm.rkS[t >> 6][t & 63] = rel_k[t];
        sm.rvS[t >> 6][t & 63] = rel_v[t];
    }

    const int rw = wid << 5;
    float qf[2][8][4];
    #pragma unroll
    for (int h = 0; h < 2; h++) {
        const float* qr0 = &qptr[(size_t)(q0 + rw + (h << 4) + qd) * D_];
        #pragma unroll
        for (int kf = 0; kf < 8; kf++) {
            qf[h][kf][0] = __ldg(&qr0[(kf << 3) + lr]);
            qf[h][kf][1] = __ldg(&qr0[(size_t)8 * D_ + (kf << 3) + lr]);
            qf[h][kf][2] = __ldg(&qr0[(kf << 3) + lr + 4]);
            qf[h][kf][3] = __ldg(&qr0[(size_t)8 * D_ + (kf << 3) + lr + 4]);
        }
    }
    __syncthreads();

    #pragma unroll
    for (int st = 0; st < 4; st++) {
        int h = st >> 1, rp = st & 1;
        int rloc = rw + (h << 4) + qd + (rp << 3);
        #pragma unroll
        for (int jb = 0; jb < NB_; jb++) {
            float acc = 0.f;
            #pragma unroll
            for (int kf = 0; kf < 8; kf++) {
                acc += qf[h][kf][rp]     * sm.rkS[jb][(kf << 3) + lr];
                acc += qf[h][kf][rp + 2] * sm.rkS[jb][(kf << 3) + lr + 4];
            }
            acc += __shfl_xor_sync(0xffffffffu, acc, 1);
            acc += __shfl_xor_sync(0xffffffffu, acc, 2);
            if (lr == 0) sm.qrelS[rloc][jb] = acc;
        }
    }
    __syncthreads();

    float O0[8][4] = {}, O1[8][4] = {};
    float lS[4] = {}, bsS[4][NB_] = {};
    const int rmin = q0 + rw;

    for (int kt = 0; kt < S_ / 32; kt++) {
        const int k0 = kt << 5;
        const int cur = kt & 1;
        CP_WAIT0();
        __syncthreads();
        if (kt + 1 < S_ / 32) { load_kv(cur ^ 1, k0 + 32); CP_COMMIT(); }

        const float (*Kc)[68] = sm.Ks[cur];
        const float (*Vc)[72] = sm.Vs[cur];

        float s0[4][4] = {}, s1[4][4] = {};
        #pragma unroll
        for (int kf = 0; kf < 8; kf++) {
            #pragma unroll
            for (int nf = 0; nf < 4; nf++) {
                float b0 = Kc[(nf << 3) + qd][(kf << 3) + lr];
                float b1 = Kc[(nf << 3) + qd][(kf << 3) + lr + 4];
                mma8f(s0[nf], qf[0][kf], b0, b1);
                mma8f(s1[nf], qf[1][kf], b0, b1);
            }
        }

        bool mixed = (k0 > rmin - 34) && (k0 < rmin + 34);

        #pragma unroll
        for (int h = 0; h < 2; h++) {
            float (*s)[4] = (h == 0) ? s0 : s1;
            int stA = h << 1, stB = stA + 1;
            int rlA = rw + (h << 4) + qd;
            int rgA = q0 + rlA, rgB = rgA + 8;
            float rsA = 0.f, rsB = 0.f;

            if (!mixed) {
                const int bkt = (k0 >= rmin + 34) ? 4 : 0;
                float cA = sm.qrelS[rlA][bkt] * ALPHA_;
                float cB = sm.qrelS[rlA + 8][bkt] * ALPHA_;
                #pragma unroll
                for (int nf = 0; nf < 4; nf++) {
                    float p0 = exp2p(fmaf(s[nf][0], ALPHA_, cA));
                    float p1 = exp2p(fmaf(s[nf][1], ALPHA_, cA));
                    float p2 = exp2p(fmaf(s[nf][2], ALPHA_, cB));
                    float p3 = exp2p(fmaf(s[nf][3], ALPHA_, cB));
                    s[nf][0] = p0; s[nf][1] = p1; s[nf][2] = p2; s[nf][3] = p3;
                    rsA += p0 + p1; rsB += p2 + p3;
                }
                lS[stA] += rsA; lS[stB] += rsB;
                bsS[stA][bkt] += rsA; bsS[stB][bkt] += rsB;
            } else {
                #pragma unroll
                for (int nf = 0; nf < 4; nf++) {
                    #pragma unroll
                    for (int e = 0; e < 4; e++) {
                        int kp = k0 + (nf << 3) + (lr << 1) + (e & 1);
                        int rg = (e < 2) ? rgA : rgB;
                        int rl = (e < 2) ? rlA : rlA + 8;
                        int jb = min(max(kp - rg, -2), 2) + 2;
                        float p = exp2p((s[nf][e] + sm.qrelS[rl][jb]) * ALPHA_);
                        s[nf][e] = p;
                        if (e < 2) { rsA += p; bsS[stA][jb] += p; }
                        else       { rsB += p; bsS[stB][jb] += p; }
                    }
                }
                lS[stA] += rsA; lS[stB] += rsB;
            }
        }

        #pragma unroll
        for (int j = 0; j < 4; j++) {
            float a0[4], a1[4];
            {
                float c0 = f2tff(s0[j][0]), c1 = f2tff(s0[j][1]);
                float c2 = f2tff(s0[j][2]), c3 = f2tff(s0[j][3]);
                float t00 = __shfl_sync(0xffffffffu, c0, src0);
                float t10 = __shfl_sync(0xffffffffu, c1, src0);
                float t20 = __shfl_sync(0xffffffffu, c2, src0);
                float t30 = __shfl_sync(0xffffffffu, c3, src0);
                float t01 = __shfl_sync(0xffffffffu, c0, src1);
                float t11 = __shfl_sync(0xffffffffu, c1, src1);
                float t21 = __shfl_sync(0xffffffffu, c2, src1);
                float t31 = __shfl_sync(0xffffffffu, c3, src1);
                a0[0] = odd ? t10 : t00; a0[1] = odd ? t30 : t20;
                a0[2] = odd ? t11 : t01; a0[3] = odd ? t31 : t21;
            }
            {
                float c0 = f2tff(s1[j][0]), c1 = f2tff(s1[j][1]);
                float c2 = f2tff(s1[j][2]), c3 = f2tff(s1[j][3]);
                float t00 = __shfl_sync(0xffffffffu, c0, src0);
                float t10 = __shfl_sync(0xffffffffu, c1, src0);
                float t20 = __shfl_sync(0xffffffffu, c2, src0);
                float t30 = __shfl_sync(0xffffffffu, c3, src0);
                float t01 = __shfl_sync(0xffffffffu, c0, src1);
                float t11 = __shfl_sync(0xffffffffu, c1, src1);
                float t21 = __shfl_sync(0xffffffffu, c2, src1);
                float t31 = __shfl_sync(0xffffffffu, c3, src1);
                a1[0] = odd ? t10 : t00; a1[1] = odd ? t30 : t20;
                a1[2] = odd ? t11 : t01; a1[3] = odd ? t31 : t21;
            }
            #pragma unroll
            for (int nf = 0; nf < 8; nf++) {
                float b0 = Vc[(j << 3) + lr][(nf << 3) + qd];
                float b1 = Vc[(j << 3) + lr + 4][(nf << 3) + qd];
                mma8f(O0[nf], a0, b0, b1);
                mma8f(O1[nf], a1, b0, b1);
            }
        }
    }

    #pragma unroll
    for (int st = 0; st < 4; st++) {
        #pragma unroll
        for (int o = 1; o <= 2; o <<= 1) {
            lS[st] += __shfl_xor_sync(0xffffffffu, lS[st], o);
            #pragma unroll
            for (int jb = 0; jb < NB_; jb++)
                bsS[st][jb] += __shfl_xor_sync(0xffffffffu, bsS[st][jb], o);
        }
    }

    const int bb = bh / H_, hh = bh % H_;
    #pragma unroll
    for (int h = 0; h < 2; h++) {
        float (*Oh)[4] = (h == 0) ? O0 : O1;
        #pragma unroll
        for (int rp = 0; rp < 2; rp++) {
            int st = (h << 1) + rp;
            float inv = 1.f / lS[st];
            int rg = q0 + rw + (h << 4) + qd + (rp << 3);
            #pragma unroll
            for (int nf = 0; nf < 8; nf++) {
                int d0 = (nf << 3) + (lr << 1);
                float o2a = 0.f, o2b = 0.f;
                #pragma unroll
                for (int jb = 0; jb < NB_; jb++) {
                    o2a += bsS[st][jb] * sm.rvS[jb][d0];
                    o2b += bsS[st][jb] * sm.rvS[jb][d0 + 1];
                }
                float2 w = make_float2(f2tff((Oh[nf][(rp << 1)] + o2a) * inv),
                                       f2tff((Oh[nf][(rp << 1) + 1] + o2b) * inv));
                *(float2*)&g_att[(((size_t)bb * S_ + rg) * H_ + hh) * D_ + d0] = w;
            }
        }
    }
}

// ---------------------------------------------------------------------------
extern "C" void kernel_launch(void* const* d_in, const int* in_sizes, int n_in,
                              void* d_out, int out_size) {
    const float* x    = (const float*)d_in[0];
    const float* Wq   = (const float*)d_in[1];
    const float* bq   = (const float*)d_in[2];
    const float* Wk   = (const float*)d_in[3];
    const float* bk   = (const float*)d_in[4];
    const float* Wv   = (const float*)d_in[5];
    const float* bv   = (const float*)d_in[6];
    const float* Wo   = (const float*)d_in[7];
    const float* bo   = (const float*)d_in[8];
    const float* relk = (const float*)d_in[9];
    const float* relv = (const float*)d_in[10];
    float* out = (float*)d_out;

    float *gq, *gk, *gv, *gatt, *gxr;
    cudaGetSymbolAddress((void**)&gq,   g_q);
    cudaGetSymbolAddress((void**)&gk,   g_k);
    cudaGetSymbolAddress((void**)&gv,   g_v);
    cudaGetSymbolAddress((void**)&gatt, g_att);
    cudaGetSymbolAddress((void**)&gxr,  g_xr);

    cudaFuncSetAttribute(gemm_qkv, cudaFuncAttributeMaxDynamicSharedMemorySize,
                         (int)sizeof(GSmem));
    cudaFuncSetAttribute(gemm_out, cudaFuncAttributeMaxDynamicSharedMemorySize,
                         (int)sizeof(GSmem));
    cudaFuncSetAttribute(attn_tf32, cudaFuncAttributeMaxDynamicSharedMemorySize,
                         (int)sizeof(ASmem));

    round_pass<<<2048, 256>>>(x, Wq, Wk, Wv, Wo);

    gemm_qkv<<<dim3(DM_ / 128, (B_ * S_) / 128, 3), 128, sizeof(GSmem)>>>(
        gxr, bq, bk, bv, gq, gk, gv);
    attn_tf32<<<dim3(S_ / 128, B_ * H_), 128, sizeof(ASmem)>>>(relk, relv);
    gemm_out<<<dim3(DM_ / 128, (B_ * S_) / 128), 128, sizeof(GSmem)>>>(gatt, bo, out);
}